// round 1
// baseline (speedup 1.0000x reference)
#include <cuda_runtime.h>
#include <cstdint>

#define NN      256
#define EE      65536
#define MMOT    65536
#define NNZ     524288
#define EENNZ   524288
#define SLOPE   0.01f

// ---------------- device scratch (static, no allocations) ----------------
__device__ int   g_is64;
__device__ float g_small[7 * 65536];   // A, x, y, G, y2, T1, T (each 256x256)
#define OFF_A   0
#define OFF_X   (1 * 65536)
#define OFF_Y   (2 * 65536)
#define OFF_G   (3 * 65536)
#define OFF_Y2  (4 * 65536)
#define OFF_T1  (5 * 65536)
#define OFF_T   (6 * 65536)
__device__ float g_Wc[256 * 64];
__device__ float g_b2[256];
__device__ float g_bc[64];
__device__ float g_dinv[256];
__device__ float g_dis[EE];
__device__ int   g_cnt_he[EE];
__device__ int   g_cnt_col[EE];
__device__ int   g_off_he[EE + 1];
__device__ int   g_off_col[EE + 1];
__device__ int   g_cur_he[EE];
__device__ int   g_cur_col[EE];
__device__ int   g_dnode[NN];
__device__ int   g_members[NNZ];
__device__ int   g_rows[EENNZ];
__device__ float g_w[(size_t)EE * 256];   // dis[e] * mean-agg rows (64 MB)
__device__ float g_v[(size_t)EE * 256];   // GCN+lin2 output per hyperedge (64 MB)

__device__ __forceinline__ int ldidx(const void* p, long long i, int is64) {
    return is64 ? (int)((const long long*)p)[i] : ((const int*)p)[i];
}
__device__ __forceinline__ float lrelu(float x) { return x >= 0.0f ? x : SLOPE * x; }

// ---------------- index dtype detection ----------------
__global__ void k_detect(const unsigned* __restrict__ p) {
    __shared__ int nz;
    if (threadIdx.x == 0) nz = 0;
    __syncthreads();
    int any = 0;
    for (int i = threadIdx.x; i < 4096; i += blockDim.x)
        any |= (p[2 * i + 1] != 0u);
    if (any) atomicOr(&nz, 1);
    __syncthreads();
    if (threadIdx.x == 0) g_is64 = nz ? 0 : 1;
}

// ---------------- init ----------------
__global__ void k_init() {
    int stride = gridDim.x * blockDim.x;
    for (int t = blockIdx.x * blockDim.x + threadIdx.x; t < EE; t += stride) {
        g_small[OFF_A + t] = 0.0f;
        g_cnt_he[t] = 0; g_cnt_col[t] = 0;
        g_cur_he[t] = 0; g_cur_col[t] = 0;
        if (t < NN) g_dnode[t] = 0;
    }
}

// ---------------- histograms ----------------
__global__ void k_hist_inc(const void* __restrict__ ei) {
    __shared__ int h[NN];
    int is64 = g_is64;
    for (int i = threadIdx.x; i < NN; i += blockDim.x) h[i] = 0;
    __syncthreads();
    int stride = gridDim.x * blockDim.x;
    for (int i = blockIdx.x * blockDim.x + threadIdx.x; i < NNZ; i += stride) {
        int src = ldidx(ei, i, is64);
        int he  = ldidx(ei, (long long)NNZ + i, is64);
        atomicAdd(&g_cnt_he[he], 1);
        atomicAdd(&h[src], 1);
    }
    __syncthreads();
    for (int i = threadIdx.x; i < NN; i += blockDim.x)
        if (h[i]) atomicAdd(&g_dnode[i], h[i]);
}

__global__ void k_hist_ee(const void* __restrict__ eei) {
    int is64 = g_is64;
    int stride = gridDim.x * blockDim.x;
    for (int j = blockIdx.x * blockDim.x + threadIdx.x; j < EENNZ; j += stride) {
        int col = ldidx(eei, (long long)EENNZ + j, is64);
        atomicAdd(&g_cnt_col[col], 1);
    }
}

// ---------------- 64K-bin exclusive scan (single block, 1024 threads x 64 bins) ----
__global__ void k_scan(int which) {
    const int* cnt = which ? g_cnt_col : g_cnt_he;
    int*       off = which ? g_off_col : g_off_he;
    __shared__ int s[1024];
    int t = threadIdx.x;
    int base = t * 64;
    int sum = 0;
    for (int i = 0; i < 64; i++) sum += cnt[base + i];
    s[t] = sum;
    __syncthreads();
    for (int o = 1; o < 1024; o <<= 1) {
        int v = (t >= o) ? s[t - o] : 0;
        __syncthreads();
        s[t] += v;
        __syncthreads();
    }
    int run = s[t] - sum;  // exclusive prefix
    for (int i = 0; i < 64; i++) { off[base + i] = run; run += cnt[base + i]; }
    if (t == 1023) off[EE] = run;
}

// ---------------- scatters into CSR ----------------
__global__ void k_scatter_inc(const void* __restrict__ ei) {
    int is64 = g_is64;
    int stride = gridDim.x * blockDim.x;
    for (int i = blockIdx.x * blockDim.x + threadIdx.x; i < NNZ; i += stride) {
        int src = ldidx(ei, i, is64);
        int he  = ldidx(ei, (long long)NNZ + i, is64);
        int pos = g_off_he[he] + atomicAdd(&g_cur_he[he], 1);
        g_members[pos] = src;
    }
}

__global__ void k_scatter_ee(const void* __restrict__ eei) {
    int is64 = g_is64;
    int stride = gridDim.x * blockDim.x;
    for (int j = blockIdx.x * blockDim.x + threadIdx.x; j < EENNZ; j += stride) {
        int row = ldidx(eei, j, is64);
        int col = ldidx(eei, (long long)EENNZ + j, is64);
        int pos = g_off_col[col] + atomicAdd(&g_cur_col[col], 1);
        g_rows[pos] = row;
    }
}

// ---------------- degree prep ----------------
__global__ void k_prep() {
    int i = blockIdx.x * blockDim.x + threadIdx.x;
    if (i < EE) g_dis[i] = rsqrtf((float)(g_cnt_col[i] + 1));  // +1 self loop
    if (i < NN) g_dinv[i] = g_dnode[i] > 0 ? 1.0f / (float)g_dnode[i] : 0.0f;
}

// ---------------- A = H B^-1 H^T accumulation (one warp per hyperedge) -----
__global__ void k_accA() {
    int w    = (blockIdx.x * blockDim.x + threadIdx.x) >> 5;
    int lane = threadIdx.x & 31;
    if (w >= EE) return;
    int s = g_off_he[w], e = g_off_he[w + 1];
    int k = e - s;
    if (k == 0) return;
    float binv = 1.0f / (float)k;
    int tot = k * k;
    for (int p = lane; p < tot; p += 32) {
        int i = p / k, j = p - i * k;
        int mi = g_members[s + i], mj = g_members[s + j];
        atomicAdd(&g_small[OFF_A + mi * 256 + mj], binv);
    }
}

// ---------------- generic small GEMM (256-scale, tiled 16x16) ----------------
__global__ void k_gemm(const float* __restrict__ A, const float* __restrict__ B,
                       float* __restrict__ C, int Mm, int Nn, int Kk,
                       const float* __restrict__ bias,
                       const float* __restrict__ rowscale,
                       int act, int transA) {
    __shared__ float As[16][17], Bs[16][17];
    int tx = threadIdx.x, ty = threadIdx.y;
    int row = blockIdx.y * 16 + ty;
    int col = blockIdx.x * 16 + tx;
    float acc = 0.0f;
    for (int kt = 0; kt < Kk; kt += 16) {
        As[ty][tx] = transA ? A[(kt + tx) * Mm + row] : A[row * Kk + kt + tx];
        Bs[ty][tx] = B[(kt + ty) * Nn + col];
        __syncthreads();
#pragma unroll
        for (int kk = 0; kk < 16; kk++) acc += As[ty][kk] * Bs[kk][tx];
        __syncthreads();
    }
    if (rowscale) acc *= rowscale[row];
    if (bias)     acc += bias[col];
    if (act)      acc = lrelu(acc);
    C[row * Nn + col] = acc;
}

// ---------------- fold biases: b2 = b_gcn@W_lin2 + b_lin2, bc = b_lin3@W_out + b_out
__global__ void k_smallvec(const float* __restrict__ bg, const float* __restrict__ Wl2,
                           const float* __restrict__ bl2, const float* __restrict__ bl3,
                           const float* __restrict__ Wo, const float* __restrict__ bo) {
    int j = threadIdx.x;
    float a = 0.0f;
    for (int k = 0; k < 256; k++) a += bg[k] * Wl2[k * 256 + j];
    g_b2[j] = a + bl2[j];
    if (j < 64) {
        float c = 0.0f;
        for (int k = 0; k < 128; k++) c += bl3[k] * Wo[k * 64 + j];
        g_bc[j] = c + bo[j];
    }
}

// ---------------- w[e] = dis[e] * mean_{members} T[src]  (block 64 thr = 1 row)
__global__ void k_u() {
    int e = blockIdx.x, tid = threadIdx.x;
    int s = g_off_he[e], en = g_off_he[e + 1];
    const float* T = &g_small[OFF_T];
    float4 acc = make_float4(0.f, 0.f, 0.f, 0.f);
    for (int m = s; m < en; m++) {
        int src = g_members[m];
        float4 v = *(const float4*)&T[src * 256 + tid * 4];
        acc.x += v.x; acc.y += v.y; acc.z += v.z; acc.w += v.w;
    }
    int k = en - s;
    float sc = (k > 0 ? 1.0f / (float)k : 0.0f) * g_dis[e];
    float4 o = make_float4(acc.x * sc, acc.y * sc, acc.z * sc, acc.w * sc);
    *(float4*)&g_w[(size_t)e * 256 + tid * 4] = o;
}

// ---------------- GCN agg (gather by col, no atomics) + lin2 bias + leaky ---
__global__ void k_agg() {
    int c = blockIdx.x, tid = threadIdx.x;
    float4 acc = *(const float4*)&g_w[(size_t)c * 256 + tid * 4];  // self loop
    int s = g_off_col[c], en = g_off_col[c + 1];
    for (int j = s; j < en; j++) {
        int r = g_rows[j];
        float4 v = *(const float4*)&g_w[(size_t)r * 256 + tid * 4];
        acc.x += v.x; acc.y += v.y; acc.z += v.z; acc.w += v.w;
    }
    float dc = g_dis[c];
    float4 b = *(const float4*)&g_b2[tid * 4];
    float4 o;
    o.x = lrelu(dc * acc.x + b.x);
    o.y = lrelu(dc * acc.y + b.y);
    o.z = lrelu(dc * acc.z + b.z);
    o.w = lrelu(dc * acc.w + b.w);
    *(float4*)&g_v[(size_t)c * 256 + tid * 4] = o;
}

// ---------------- motif min (3 members) fused with GEMM [32 motifs/block] ----
// out[t] = min(y2[e0],y2[e1],y2[e2]) @ Wc + bc
__global__ void k_motif(const void* __restrict__ mei, float* __restrict__ out) {
    __shared__ float sM[256 * 36];   // [k][motif], pad 36 for banks+alignment
    int tid = threadIdx.x;           // 128 threads
    int is64 = g_is64;
    int mbase = blockIdx.x * 32;
    for (int mm = 0; mm < 32; mm++) {
        long long t3 = 3LL * (mbase + mm);
        int e0 = ldidx(mei, t3,     is64);
        int e1 = ldidx(mei, t3 + 1, is64);
        int e2 = ldidx(mei, t3 + 2, is64);
        const float* r0 = &g_v[(size_t)e0 * 256];
        const float* r1 = &g_v[(size_t)e1 * 256];
        const float* r2 = &g_v[(size_t)e2 * 256];
        for (int c = tid; c < 256; c += 128) {
            float v = fminf(fminf(r0[c], r1[c]), r2[c]);
            sM[c * 36 + mm] = v;
        }
    }
    __syncthreads();
    int c0 = (tid & 15) * 4;   // 4 output cols
    int m0 = (tid >> 4) * 4;   // 4 motifs
    float acc[4][4];
#pragma unroll
    for (int a = 0; a < 4; a++)
#pragma unroll
        for (int b = 0; b < 4; b++) acc[a][b] = 0.0f;
#pragma unroll 4
    for (int k = 0; k < 256; k++) {
        float4 wv = *(const float4*)&g_Wc[k * 64 + c0];
        float4 mv = *(const float4*)&sM[k * 36 + m0];
        acc[0][0] += mv.x * wv.x; acc[0][1] += mv.x * wv.y; acc[0][2] += mv.x * wv.z; acc[0][3] += mv.x * wv.w;
        acc[1][0] += mv.y * wv.x; acc[1][1] += mv.y * wv.y; acc[1][2] += mv.y * wv.z; acc[1][3] += mv.y * wv.w;
        acc[2][0] += mv.z * wv.x; acc[2][1] += mv.z * wv.y; acc[2][2] += mv.z * wv.z; acc[2][3] += mv.z * wv.w;
        acc[3][0] += mv.w * wv.x; acc[3][1] += mv.w * wv.y; acc[3][2] += mv.w * wv.z; acc[3][3] += mv.w * wv.w;
    }
    float4 bc = *(const float4*)&g_bc[c0];
#pragma unroll
    for (int a = 0; a < 4; a++) {
        int t = mbase + m0 + a;
        float4 o = make_float4(acc[a][0] + bc.x, acc[a][1] + bc.y,
                               acc[a][2] + bc.z, acc[a][3] + bc.w);
        *(float4*)&out[(size_t)t * 64 + c0] = o;
    }
}

// ---------------- host ----------------
extern "C" void kernel_launch(void* const* d_in, const int* in_sizes, int n_in,
                              void* d_out, int out_size) {
    const float* node_embeds = (const float*)d_in[0];
    const float* W_hg   = (const float*)d_in[1];
    const float* b_hg   = (const float*)d_in[2];
    const float* W_lin  = (const float*)d_in[3];
    const float* b_lin  = (const float*)d_in[4];
    const float* W_gcn  = (const float*)d_in[5];
    const float* b_gcn  = (const float*)d_in[6];
    const float* W_lin2 = (const float*)d_in[7];
    const float* b_lin2 = (const float*)d_in[8];
    const float* W_lin3 = (const float*)d_in[9];
    const float* b_lin3 = (const float*)d_in[10];
    const float* W_out  = (const float*)d_in[11];
    const float* b_out  = (const float*)d_in[12];
    const void*  ei     = d_in[13];
    const void*  eei    = d_in[14];
    const void*  mei    = d_in[15];
    float* out = (float*)d_out;

    float* smallp = nullptr;
    float* Wcp    = nullptr;
    float* dinvp  = nullptr;
    cudaGetSymbolAddress((void**)&smallp, g_small);
    cudaGetSymbolAddress((void**)&Wcp,    g_Wc);
    cudaGetSymbolAddress((void**)&dinvp,  g_dinv);
    float* Ap  = smallp + OFF_A;
    float* xp  = smallp + OFF_X;
    float* yp  = smallp + OFF_Y;
    float* Gp  = smallp + OFF_G;
    float* y2p = smallp + OFF_Y2;
    float* T1p = smallp + OFF_T1;
    float* Tp  = smallp + OFF_T;

    k_detect<<<1, 256>>>((const unsigned*)ei);
    k_init<<<256, 256>>>();
    k_hist_inc<<<1024, 256>>>(ei);
    k_hist_ee<<<1024, 256>>>(eei);
    k_scan<<<1, 1024>>>(0);
    k_scan<<<1, 1024>>>(1);
    k_scatter_inc<<<1024, 256>>>(ei);
    k_scatter_ee<<<1024, 256>>>(eei);
    k_prep<<<256, 256>>>();
    k_accA<<<8192, 256>>>();

    dim3 b16(16, 16);
    // x = node_embeds @ W_hg
    k_gemm<<<dim3(16, 16), b16>>>(node_embeds, W_hg, xp, 256, 256, 256, nullptr, nullptr, 0, 0);
    // y = leaky( dinv * (A @ x) + b_hg )
    k_gemm<<<dim3(16, 16), b16>>>(Ap, xp, yp, 256, 256, 256, b_hg, dinvp, 1, 0);
    // G = y^T @ y
    k_gemm<<<dim3(16, 16), b16>>>(yp, yp, Gp, 256, 256, 256, nullptr, nullptr, 0, 1);
    // y2 = leaky( G @ W_lin + b_lin )
    k_gemm<<<dim3(16, 16), b16>>>(Gp, W_lin, y2p, 256, 256, 256, b_lin, nullptr, 1, 0);
    // T = y2 @ W_gcn @ W_lin2
    k_gemm<<<dim3(16, 16), b16>>>(y2p, W_gcn, T1p, 256, 256, 256, nullptr, nullptr, 0, 0);
    k_gemm<<<dim3(16, 16), b16>>>(T1p, W_lin2, Tp, 256, 256, 256, nullptr, nullptr, 0, 0);
    // Wc = W_lin3 @ W_out
    k_gemm<<<dim3(4, 16), b16>>>(W_lin3, W_out, Wcp, 256, 64, 128, nullptr, nullptr, 0, 0);
    k_smallvec<<<1, 256>>>(b_gcn, W_lin2, b_lin2, b_lin3, W_out, b_out);

    k_u<<<65536, 64>>>();
    k_agg<<<65536, 64>>>();
    k_motif<<<2048, 128>>>(mei, out);
}

// round 2
// speedup vs baseline: 1.1505x; 1.1505x over previous
#include <cuda_runtime.h>
#include <cstdint>

#define NN      256
#define EE      65536
#define MMOT    65536
#define NNZ     524288
#define EENNZ   524288
#define SLOPE   0.01f

// ---------------- device scratch (static, no allocations) ----------------
__device__ int   g_is64;
__device__ float g_small[7 * 65536];   // A, x, y, G, y2, T1, T (each 256x256)
#define OFF_A   0
#define OFF_X   (1 * 65536)
#define OFF_Y   (2 * 65536)
#define OFF_G   (3 * 65536)
#define OFF_Y2  (4 * 65536)
#define OFF_T1  (5 * 65536)
#define OFF_T   (6 * 65536)
__device__ float g_Wc[256 * 64];
__device__ float g_b2[256];
__device__ float g_bc[64];
__device__ float g_dinv[256];
__device__ float g_dis[EE];
__device__ int   g_cnt_he[EE];
__device__ int   g_cnt_col[EE];
__device__ int   g_off_he[EE + 1];
__device__ int   g_off_col[EE + 1];
__device__ int   g_cur_he[EE];
__device__ int   g_cur_col[EE];
__device__ int   g_dnode[NN];
__device__ int   g_members[NNZ];
__device__ int   g_rows[EENNZ];
__device__ float g_w[(size_t)EE * 256];   // dis[e] * mean-agg rows (64 MB)
__device__ float g_v[(size_t)EE * 256];   // GCN+lin2 output per hyperedge (64 MB)

__device__ __forceinline__ int ldidx(const void* p, long long i, int is64) {
    return is64 ? (int)((const long long*)p)[i] : ((const int*)p)[i];
}
__device__ __forceinline__ float lrelu(float x) { return x >= 0.0f ? x : SLOPE * x; }

// ---------------- init + index dtype detection (fused) ----------------
__global__ void k_initdet(const unsigned* __restrict__ p) {
    int stride = gridDim.x * blockDim.x;
    for (int t = blockIdx.x * blockDim.x + threadIdx.x; t < EE; t += stride) {
        g_small[OFF_A + t] = 0.0f;
        g_cnt_he[t] = 0; g_cnt_col[t] = 0;
        g_cur_he[t] = 0; g_cur_col[t] = 0;
        if (t < NN) g_dnode[t] = 0;
    }
    if (blockIdx.x == 0) {
        __shared__ int nz;
        if (threadIdx.x == 0) nz = 0;
        __syncthreads();
        int any = 0;
        for (int i = threadIdx.x; i < 4096; i += blockDim.x)
            any |= (p[2 * i + 1] != 0u);
        if (any) atomicOr(&nz, 1);
        __syncthreads();
        if (threadIdx.x == 0) g_is64 = nz ? 0 : 1;
    }
}

// ---------------- fused histograms ----------------
__global__ void k_hist(const void* __restrict__ ei, const void* __restrict__ eei) {
    int is64 = g_is64;
    __shared__ int h[NN];
    if (blockIdx.x < 1024) {
        for (int i = threadIdx.x; i < NN; i += blockDim.x) h[i] = 0;
        __syncthreads();
        int stride = 1024 * blockDim.x;
        for (int i = blockIdx.x * blockDim.x + threadIdx.x; i < NNZ; i += stride) {
            int src = ldidx(ei, i, is64);
            int he  = ldidx(ei, (long long)NNZ + i, is64);
            atomicAdd(&g_cnt_he[he], 1);
            atomicAdd(&h[src], 1);
        }
        __syncthreads();
        for (int i = threadIdx.x; i < NN; i += blockDim.x)
            if (h[i]) atomicAdd(&g_dnode[i], h[i]);
    } else {
        int b = blockIdx.x - 1024;
        int stride = 1024 * blockDim.x;
        for (int j = b * blockDim.x + threadIdx.x; j < EENNZ; j += stride) {
            int col = ldidx(eei, (long long)EENNZ + j, is64);
            atomicAdd(&g_cnt_col[col], 1);
        }
    }
}

// ------- 64K-bin exclusive scan (2 blocks: one per CSR) + degree prep -------
__global__ void k_scan() {
    int which = blockIdx.x;
    const int* cnt = which ? g_cnt_col : g_cnt_he;
    int*       off = which ? g_off_col : g_off_he;
    __shared__ int s[1024];
    int t = threadIdx.x;
    int base = t * 64;
    int sum = 0;
#pragma unroll 8
    for (int i = 0; i < 64; i++) sum += cnt[base + i];
    s[t] = sum;
    __syncthreads();
    for (int o = 1; o < 1024; o <<= 1) {
        int v = (t >= o) ? s[t - o] : 0;
        __syncthreads();
        s[t] += v;
        __syncthreads();
    }
    int run = s[t] - sum;  // exclusive prefix
    for (int i = 0; i < 64; i++) { off[base + i] = run; run += cnt[base + i]; }
    if (t == 1023) off[EE] = run;
    // fold degree prep in
    if (which) {
        for (int i = t; i < EE; i += 1024)
            g_dis[i] = rsqrtf((float)(g_cnt_col[i] + 1));  // +1 self loop
    } else {
        if (t < NN) g_dinv[t] = g_dnode[t] > 0 ? 1.0f / (float)g_dnode[t] : 0.0f;
    }
}

// ---------------- fused scatters into CSR ----------------
__global__ void k_scatter(const void* __restrict__ ei, const void* __restrict__ eei) {
    int is64 = g_is64;
    int stride = 1024 * blockDim.x;
    if (blockIdx.x < 1024) {
        for (int i = blockIdx.x * blockDim.x + threadIdx.x; i < NNZ; i += stride) {
            int src = ldidx(ei, i, is64);
            int he  = ldidx(ei, (long long)NNZ + i, is64);
            int pos = g_off_he[he] + atomicAdd(&g_cur_he[he], 1);
            g_members[pos] = src;
        }
    } else {
        int b = blockIdx.x - 1024;
        for (int j = b * blockDim.x + threadIdx.x; j < EENNZ; j += stride) {
            int row = ldidx(eei, j, is64);
            int col = ldidx(eei, (long long)EENNZ + j, is64);
            int pos = g_off_col[col] + atomicAdd(&g_cur_col[col], 1);
            g_rows[pos] = row;
        }
    }
}

// ------- diagonal of A via shared-memory float histogram (kills contention) --
__global__ void k_diag(const void* __restrict__ ei) {
    __shared__ float h[NN];
    for (int i = threadIdx.x; i < NN; i += blockDim.x) h[i] = 0.0f;
    __syncthreads();
    int is64 = g_is64;
    int stride = gridDim.x * blockDim.x;
    for (int i = blockIdx.x * blockDim.x + threadIdx.x; i < NNZ; i += stride) {
        int src = ldidx(ei, i, is64);
        int he  = ldidx(ei, (long long)NNZ + i, is64);
        atomicAdd(&h[src], 1.0f / (float)g_cnt_he[he]);
    }
    __syncthreads();
    for (int i = threadIdx.x; i < NN; i += blockDim.x)
        if (h[i] != 0.0f) atomicAdd(&g_small[OFF_A + i * 256 + i], h[i]);
}

// -------- A = H B^-1 H^T off-diagonal accumulation (one warp per hyperedge) --
__global__ void k_accA() {
    int w    = (blockIdx.x * blockDim.x + threadIdx.x) >> 5;
    int lane = threadIdx.x & 31;
    if (w >= EE) return;
    int s = g_off_he[w], e = g_off_he[w + 1];
    int k = e - s;
    if (k <= 1) return;
    float binv = 1.0f / (float)k;
    int km1 = k - 1;
    int tot = k * km1;
    for (int p = lane; p < tot; p += 32) {
        int i = p / km1, j = p - i * km1;
        if (j >= i) j++;
        int mi = g_members[s + i], mj = g_members[s + j];
        atomicAdd(&g_small[OFF_A + mi * 256 + mj], binv);
    }
}

// ---------------- generic small GEMM (256-scale, tiled 16x16) ----------------
__global__ void k_gemm(const float* __restrict__ A, const float* __restrict__ B,
                       float* __restrict__ C, int Mm, int Nn, int Kk,
                       const float* __restrict__ bias,
                       const float* __restrict__ rowscale,
                       int act, int transA) {
    __shared__ float As[16][17], Bs[16][17];
    int tx = threadIdx.x, ty = threadIdx.y;
    int row = blockIdx.y * 16 + ty;
    int col = blockIdx.x * 16 + tx;
    float acc = 0.0f;
    for (int kt = 0; kt < Kk; kt += 16) {
        As[ty][tx] = transA ? A[(kt + tx) * Mm + row] : A[row * Kk + kt + tx];
        Bs[ty][tx] = B[(kt + ty) * Nn + col];
        __syncthreads();
#pragma unroll
        for (int kk = 0; kk < 16; kk++) acc += As[ty][kk] * Bs[kk][tx];
        __syncthreads();
    }
    if (rowscale) acc *= rowscale[row];
    if (bias)     acc += bias[col];
    if (act)      acc = lrelu(acc);
    C[row * Nn + col] = acc;
}

// ---------------- fold biases: b2 = b_gcn@W_lin2 + b_lin2, bc = b_lin3@W_out + b_out
__global__ void k_smallvec(const float* __restrict__ bg, const float* __restrict__ Wl2,
                           const float* __restrict__ bl2, const float* __restrict__ bl3,
                           const float* __restrict__ Wo, const float* __restrict__ bo) {
    int j = threadIdx.x;
    float a = 0.0f;
    for (int k = 0; k < 256; k++) a += bg[k] * Wl2[k * 256 + j];
    g_b2[j] = a + bl2[j];
    if (j < 64) {
        float c = 0.0f;
        for (int k = 0; k < 128; k++) c += bl3[k] * Wo[k * 64 + j];
        g_bc[j] = c + bo[j];
    }
}

// ------ w[e] = dis[e] * mean_{members} T[src]  (4 edges / 256-thr block) -----
__global__ void k_u() {
    int e   = blockIdx.x * 4 + (threadIdx.x >> 6);
    int t   = threadIdx.x & 63;
    int s = g_off_he[e], en = g_off_he[e + 1];
    const float* __restrict__ T = &g_small[OFF_T];
    float4 acc = make_float4(0.f, 0.f, 0.f, 0.f);
    int m = s;
    for (; m + 4 <= en; m += 4) {
        int i0 = g_members[m], i1 = g_members[m + 1];
        int i2 = g_members[m + 2], i3 = g_members[m + 3];
        float4 a = *(const float4*)&T[i0 * 256 + t * 4];
        float4 b = *(const float4*)&T[i1 * 256 + t * 4];
        float4 c = *(const float4*)&T[i2 * 256 + t * 4];
        float4 d = *(const float4*)&T[i3 * 256 + t * 4];
        acc.x += (a.x + b.x) + (c.x + d.x);
        acc.y += (a.y + b.y) + (c.y + d.y);
        acc.z += (a.z + b.z) + (c.z + d.z);
        acc.w += (a.w + b.w) + (c.w + d.w);
    }
    for (; m < en; m++) {
        int src = g_members[m];
        float4 v = *(const float4*)&T[src * 256 + t * 4];
        acc.x += v.x; acc.y += v.y; acc.z += v.z; acc.w += v.w;
    }
    int k = en - s;
    float sc = (k > 0 ? 1.0f / (float)k : 0.0f) * g_dis[e];
    float4 o = make_float4(acc.x * sc, acc.y * sc, acc.z * sc, acc.w * sc);
    *(float4*)&g_w[(size_t)e * 256 + t * 4] = o;
}

// --- GCN agg (gather by col, no atomics) + lin2 bias + leaky (4 cols/block) --
__global__ void k_agg() {
    int c = blockIdx.x * 4 + (threadIdx.x >> 6);
    int t = threadIdx.x & 63;
    float4 acc = *(const float4*)&g_w[(size_t)c * 256 + t * 4];  // self loop
    int s = g_off_col[c], en = g_off_col[c + 1];
    int j = s;
    for (; j + 4 <= en; j += 4) {
        int r0 = g_rows[j], r1 = g_rows[j + 1], r2 = g_rows[j + 2], r3 = g_rows[j + 3];
        float4 a = *(const float4*)&g_w[(size_t)r0 * 256 + t * 4];
        float4 b = *(const float4*)&g_w[(size_t)r1 * 256 + t * 4];
        float4 cc = *(const float4*)&g_w[(size_t)r2 * 256 + t * 4];
        float4 d = *(const float4*)&g_w[(size_t)r3 * 256 + t * 4];
        acc.x += (a.x + b.x) + (cc.x + d.x);
        acc.y += (a.y + b.y) + (cc.y + d.y);
        acc.z += (a.z + b.z) + (cc.z + d.z);
        acc.w += (a.w + b.w) + (cc.w + d.w);
    }
    for (; j < en; j++) {
        int r = g_rows[j];
        float4 v = *(const float4*)&g_w[(size_t)r * 256 + t * 4];
        acc.x += v.x; acc.y += v.y; acc.z += v.z; acc.w += v.w;
    }
    float dc = g_dis[c];
    float4 b = *(const float4*)&g_b2[t * 4];
    float4 o;
    o.x = lrelu(dc * acc.x + b.x);
    o.y = lrelu(dc * acc.y + b.y);
    o.z = lrelu(dc * acc.z + b.z);
    o.w = lrelu(dc * acc.w + b.w);
    *(float4*)&g_v[(size_t)c * 256 + t * 4] = o;
}

// ---------------- motif min (3 members) fused with GEMM [32 motifs/block] ----
__global__ void k_motif(const void* __restrict__ mei, float* __restrict__ out) {
    __shared__ float sM[256 * 36];   // [k][motif], pad 36
    __shared__ int sIdx[96];
    int tid = threadIdx.x;           // 128 threads
    int is64 = g_is64;
    int mbase = blockIdx.x * 32;
    if (tid < 96)
        sIdx[tid] = ldidx(mei, 3LL * mbase + tid, is64);
    __syncthreads();
    for (int mm = 0; mm < 32; mm++) {
        const float* __restrict__ r0 = &g_v[(size_t)sIdx[3 * mm]     * 256];
        const float* __restrict__ r1 = &g_v[(size_t)sIdx[3 * mm + 1] * 256];
        const float* __restrict__ r2 = &g_v[(size_t)sIdx[3 * mm + 2] * 256];
        for (int c = tid; c < 256; c += 128) {
            float v = fminf(fminf(r0[c], r1[c]), r2[c]);
            sM[c * 36 + mm] = v;
        }
    }
    __syncthreads();
    int c0 = (tid & 15) * 4;   // 4 output cols
    int m0 = (tid >> 4) * 4;   // 4 motifs
    float acc[4][4];
#pragma unroll
    for (int a = 0; a < 4; a++)
#pragma unroll
        for (int b = 0; b < 4; b++) acc[a][b] = 0.0f;
#pragma unroll 4
    for (int k = 0; k < 256; k++) {
        float4 wv = *(const float4*)&g_Wc[k * 64 + c0];
        float4 mv = *(const float4*)&sM[k * 36 + m0];
        acc[0][0] += mv.x * wv.x; acc[0][1] += mv.x * wv.y; acc[0][2] += mv.x * wv.z; acc[0][3] += mv.x * wv.w;
        acc[1][0] += mv.y * wv.x; acc[1][1] += mv.y * wv.y; acc[1][2] += mv.y * wv.z; acc[1][3] += mv.y * wv.w;
        acc[2][0] += mv.z * wv.x; acc[2][1] += mv.z * wv.y; acc[2][2] += mv.z * wv.z; acc[2][3] += mv.z * wv.w;
        acc[3][0] += mv.w * wv.x; acc[3][1] += mv.w * wv.y; acc[3][2] += mv.w * wv.z; acc[3][3] += mv.w * wv.w;
    }
    float4 bc = *(const float4*)&g_bc[c0];
#pragma unroll
    for (int a = 0; a < 4; a++) {
        int t = mbase + m0 + a;
        float4 o = make_float4(acc[a][0] + bc.x, acc[a][1] + bc.y,
                               acc[a][2] + bc.z, acc[a][3] + bc.w);
        *(float4*)&out[(size_t)t * 64 + c0] = o;
    }
}

// ---------------- host ----------------
extern "C" void kernel_launch(void* const* d_in, const int* in_sizes, int n_in,
                              void* d_out, int out_size) {
    const float* node_embeds = (const float*)d_in[0];
    const float* W_hg   = (const float*)d_in[1];
    const float* b_hg   = (const float*)d_in[2];
    const float* W_lin  = (const float*)d_in[3];
    const float* b_lin  = (const float*)d_in[4];
    const float* W_gcn  = (const float*)d_in[5];
    const float* b_gcn  = (const float*)d_in[6];
    const float* W_lin2 = (const float*)d_in[7];
    const float* b_lin2 = (const float*)d_in[8];
    const float* W_lin3 = (const float*)d_in[9];
    const float* b_lin3 = (const float*)d_in[10];
    const float* W_out  = (const float*)d_in[11];
    const float* b_out  = (const float*)d_in[12];
    const void*  ei     = d_in[13];
    const void*  eei    = d_in[14];
    const void*  mei    = d_in[15];
    float* out = (float*)d_out;

    float* smallp = nullptr;
    float* Wcp    = nullptr;
    float* dinvp  = nullptr;
    cudaGetSymbolAddress((void**)&smallp, g_small);
    cudaGetSymbolAddress((void**)&Wcp,    g_Wc);
    cudaGetSymbolAddress((void**)&dinvp,  g_dinv);
    float* Ap  = smallp + OFF_A;
    float* xp  = smallp + OFF_X;
    float* yp  = smallp + OFF_Y;
    float* Gp  = smallp + OFF_G;
    float* y2p = smallp + OFF_Y2;
    float* T1p = smallp + OFF_T1;
    float* Tp  = smallp + OFF_T;

    k_initdet<<<256, 256>>>((const unsigned*)ei);
    k_hist<<<2048, 256>>>(ei, eei);
    k_scan<<<2, 1024>>>();
    k_scatter<<<2048, 256>>>(ei, eei);
    k_diag<<<512, 256>>>(ei);
    k_accA<<<8192, 256>>>();

    dim3 b16(16, 16);
    // x = node_embeds @ W_hg
    k_gemm<<<dim3(16, 16), b16>>>(node_embeds, W_hg, xp, 256, 256, 256, nullptr, nullptr, 0, 0);
    // y = leaky( dinv * (A @ x) + b_hg )
    k_gemm<<<dim3(16, 16), b16>>>(Ap, xp, yp, 256, 256, 256, b_hg, dinvp, 1, 0);
    // G = y^T @ y
    k_gemm<<<dim3(16, 16), b16>>>(yp, yp, Gp, 256, 256, 256, nullptr, nullptr, 0, 1);
    // y2 = leaky( G @ W_lin + b_lin )
    k_gemm<<<dim3(16, 16), b16>>>(Gp, W_lin, y2p, 256, 256, 256, b_lin, nullptr, 1, 0);
    // T = y2 @ W_gcn @ W_lin2
    k_gemm<<<dim3(16, 16), b16>>>(y2p, W_gcn, T1p, 256, 256, 256, nullptr, nullptr, 0, 0);
    k_gemm<<<dim3(16, 16), b16>>>(T1p, W_lin2, Tp, 256, 256, 256, nullptr, nullptr, 0, 0);
    // Wc = W_lin3 @ W_out
    k_gemm<<<dim3(4, 16), b16>>>(W_lin3, W_out, Wcp, 256, 64, 128, nullptr, nullptr, 0, 0);
    k_smallvec<<<1, 256>>>(b_gcn, W_lin2, b_lin2, b_lin3, W_out, b_out);

    k_u<<<16384, 256>>>();
    k_agg<<<16384, 256>>>();
    k_motif<<<2048, 128>>>(mei, out);
}